// round 14
// baseline (speedup 1.0000x reference)
#include <cuda_runtime.h>
#include <cuda_bf16.h>

// ---------------- problem dims ----------------
#define NB     2
#define SEQ    1024
#define DIM    1024
#define NH     16
#define NKV    4
#define HSZ    64
#define NLAYER 6
#define VOCAB  32000
#define FFD    4096
#define NTOK   (NB*SEQ)          // 2048
#define KVD    (NKV*HSZ)         // 256
#define QKVD   (DIM + 2*KVD)     // 1536

typedef __nv_bfloat16 bf16;

// ---------------- scratch (256B-aligned) ----------------
__device__ __align__(256) float g_x  [NTOK*DIM];
__device__ __align__(256) float g_qkv[NTOK*QKVD];
__device__ __align__(256) bf16 g_h_hi [NTOK*DIM];
__device__ __align__(256) bf16 g_h_lo [NTOK*DIM];
__device__ __align__(256) bf16 g_y_hi [NTOK*DIM];
__device__ __align__(256) bf16 g_y_lo [NTOK*DIM];
__device__ __align__(256) bf16 g_ff_hi[NTOK*FFD];
__device__ __align__(256) bf16 g_ff_lo[NTOK*FFD];
__device__ __align__(256) bf16 g_wqkv_hi[NLAYER*DIM*QKVD];
__device__ __align__(256) bf16 g_wqkv_lo[NLAYER*DIM*QKVD];
__device__ __align__(256) bf16 g_wo_hi  [NLAYER*DIM*DIM];
__device__ __align__(256) bf16 g_wo_lo  [NLAYER*DIM*DIM];
__device__ __align__(256) bf16 g_w1_hi  [NLAYER*DIM*FFD];
__device__ __align__(256) bf16 g_w1_lo  [NLAYER*DIM*FFD];
__device__ __align__(256) bf16 g_w2_hi  [NLAYER*FFD*DIM];
__device__ __align__(256) bf16 g_w2_lo  [NLAYER*FFD*DIM];
__device__ __align__(256) bf16 g_wlm_hi [DIM*VOCAB];
__device__ __align__(256) bf16 g_wlm_lo [DIM*VOCAB];

// ---------------- helpers ----------------
__device__ __forceinline__ unsigned packbf2(float a, float b) {
    __nv_bfloat162 t = __floats2bfloat162_rn(a, b);
    return *(unsigned*)&t;
}
__device__ __forceinline__ void split2(float a, float b, unsigned& hi, unsigned& lo) {
    bf16 ha = __float2bfloat16(a), hb = __float2bfloat16(b);
    float la = a - __bfloat162float(ha);
    float lb = b - __bfloat162float(hb);
    __nv_bfloat162 h2 = __halves2bfloat162(ha, hb);
    hi = *(unsigned*)&h2;
    lo = packbf2(la, lb);
}

// ---------------- embedding ----------------
__global__ void embed_kernel(const int* __restrict__ tok, const float* __restrict__ te,
                             const float* __restrict__ pe, float* __restrict__ x) {
    int idx = blockIdx.x * 256 + threadIdx.x;
    int row = idx >> 10;
    int d   = idx & (DIM - 1);
    int t   = row & (SEQ - 1);
    x[idx] = te[(size_t)tok[row] * DIM + d] + pe[t * DIM + d];
}

// ---------------- split fp32 -> bf16 hi/lo (bulk, float4) ----------------
__global__ void split_kernel(const float* __restrict__ src, bf16* __restrict__ hi,
                             bf16* __restrict__ lo, int n4) {
    int i = blockIdx.x * 256 + threadIdx.x;
    if (i >= n4) return;
    float4 v = ((const float4*)src)[i];
    uint2 ph, pl;
    split2(v.x, v.y, ph.x, pl.x);
    split2(v.z, v.w, ph.y, pl.y);
    ((uint2*)hi)[i] = ph;
    ((uint2*)lo)[i] = pl;
}

// ---------------- concat Wq|Wk|Wv (all layers) + split ----------------
__global__ void concat_split_qkv(const float* __restrict__ Wq, const float* __restrict__ Wk,
                                 const float* __restrict__ Wv,
                                 bf16* __restrict__ hi, bf16* __restrict__ lo) {
    int idx4 = blockIdx.x * 256 + threadIdx.x;
    if (idx4 >= NLAYER * DIM * (QKVD / 4)) return;
    int l   = idx4 / (DIM * (QKVD / 4));
    int r   = idx4 % (DIM * (QKVD / 4));
    int row = r / (QKVD / 4);
    int col = (r % (QKVD / 4)) * 4;
    float4 v;
    if (col < DIM)            v = *(const float4*)(Wq + ((size_t)l * DIM + row) * DIM + col);
    else if (col < DIM + KVD) v = *(const float4*)(Wk + ((size_t)l * DIM + row) * KVD + (col - DIM));
    else                      v = *(const float4*)(Wv + ((size_t)l * DIM + row) * KVD + (col - DIM - KVD));
    uint2 ph, pl;
    split2(v.x, v.y, ph.x, pl.x);
    split2(v.z, v.w, ph.y, pl.y);
    size_t o = ((size_t)l * DIM + row) * QKVD + col;
    *(uint2*)(hi + o) = ph;
    *(uint2*)(lo + o) = pl;
}

// ---------------- layernorm -> split bf16 hi/lo ----------------
__global__ __launch_bounds__(256) void ln_kernel(const float* __restrict__ x,
                                                 const float* __restrict__ g,
                                                 const float* __restrict__ b,
                                                 bf16* __restrict__ yhi,
                                                 bf16* __restrict__ ylo) {
    int row = blockIdx.x;
    int tid = threadIdx.x;
    const float* xr = x + (size_t)row * DIM;
    float4 v = *(const float4*)(xr + tid * 4);
    float sum = v.x + v.y + v.z + v.w;
    float sq  = v.x*v.x + v.y*v.y + v.z*v.z + v.w*v.w;
    #pragma unroll
    for (int o = 16; o > 0; o >>= 1) {
        sum += __shfl_xor_sync(0xffffffffu, sum, o);
        sq  += __shfl_xor_sync(0xffffffffu, sq,  o);
    }
    __shared__ float sh[18];
    int wid = tid >> 5, lane = tid & 31;
    if (lane == 0) { sh[wid] = sum; sh[8 + wid] = sq; }
    __syncthreads();
    if (tid == 0) {
        float a = 0.f, c = 0.f;
        #pragma unroll
        for (int w = 0; w < 8; w++) { a += sh[w]; c += sh[8 + w]; }
        float mu  = a * (1.0f / DIM);
        float var = c * (1.0f / DIM) - mu * mu;
        sh[16] = mu;
        sh[17] = rsqrtf(var + 1e-5f);
    }
    __syncthreads();
    float mu = sh[16], rstd = sh[17];
    float4 gg = *(const float4*)(g + tid * 4);
    float4 bb = *(const float4*)(b + tid * 4);
    float o0 = (v.x - mu) * rstd * gg.x + bb.x;
    float o1 = (v.y - mu) * rstd * gg.y + bb.y;
    float o2 = (v.z - mu) * rstd * gg.z + bb.z;
    float o3 = (v.w - mu) * rstd * gg.w + bb.w;
    uint2 ph, pl;
    split2(o0, o1, ph.x, pl.x);
    split2(o2, o3, ph.y, pl.y);
    *(uint2*)(yhi + (size_t)row * DIM + tid * 4) = ph;
    *(uint2*)(ylo + (size_t)row * DIM + tid * 4) = pl;
}

// =====================================================================
// bf16 split-GEMM — 512 threads / 16 warps (4M x 4N, 32x32 warp tiles),
// BK=32, 3-stage cp.async pipeline, __launch_bounds__(512,2) -> 2 CTA/SM
// (50% occupancy, 4 warps per SMSP), M-fastest grid (L2 reuse).
// C = (Ah+Al)(MxK) @ (Bh+Bl)(KxN), 3-term fp32 acc.
// EPI: 0 plain, 1 +bias, 3 +bias+res, 4 +bias+relu -> bf16 hi/lo
// =====================================================================
#define BK     32
#define SPADA  40
#define SPADB  136
#define NSTAGE 3

__device__ __forceinline__ void mma16816(float* c, const unsigned* a, const unsigned* b) {
    asm volatile(
        "mma.sync.aligned.m16n8k16.row.col.f32.bf16.bf16.f32 "
        "{%0,%1,%2,%3}, {%4,%5,%6,%7}, {%8,%9}, {%0,%1,%2,%3};\n"
        : "+f"(c[0]), "+f"(c[1]), "+f"(c[2]), "+f"(c[3])
        : "r"(a[0]), "r"(a[1]), "r"(a[2]), "r"(a[3]), "r"(b[0]), "r"(b[1]));
}
__device__ __forceinline__ void ldsm4(unsigned* r, unsigned addr) {
    asm volatile("ldmatrix.sync.aligned.m8n8.x4.shared.b16 {%0,%1,%2,%3}, [%4];\n"
                 : "=r"(r[0]), "=r"(r[1]), "=r"(r[2]), "=r"(r[3]) : "r"(addr));
}
__device__ __forceinline__ void ldsm4t(unsigned* r, unsigned addr) {
    asm volatile("ldmatrix.sync.aligned.m8n8.x4.trans.shared.b16 {%0,%1,%2,%3}, [%4];\n"
                 : "=r"(r[0]), "=r"(r[1]), "=r"(r[2]), "=r"(r[3]) : "r"(addr));
}
__device__ __forceinline__ void cpa16(unsigned dst, const void* src) {
    asm volatile("cp.async.cg.shared.global [%0], [%1], 16;\n" :: "r"(dst), "l"(src) : "memory");
}
__device__ __forceinline__ void cpa_commit() {
    asm volatile("cp.async.commit_group;\n" ::: "memory");
}
template <int Npend>
__device__ __forceinline__ void cpa_wait() {
    asm volatile("cp.async.wait_group %0;\n" :: "n"(Npend) : "memory");
}

template <int EPI>
__global__ __launch_bounds__(512, 2) void gemm_bf(const bf16* __restrict__ Ah_g,
                                                  const bf16* __restrict__ Al_g,
                                                  const bf16* __restrict__ Bh_g,
                                                  const bf16* __restrict__ Bl_g,
                                                  const float* __restrict__ bias,
                                                  const float* __restrict__ res,
                                                  float* __restrict__ C,
                                                  bf16* __restrict__ Chi,
                                                  bf16* __restrict__ Clo,
                                                  int M, int N, int K) {
    __shared__ __align__(16) bf16 Ah[NSTAGE][128][SPADA], Al[NSTAGE][128][SPADA];
    __shared__ __align__(16) bf16 Bh[NSTAGE][BK][SPADB],  Bl[NSTAGE][BK][SPADB];

    int tid = threadIdx.x;
    // M-fastest grid: concurrent CTAs share B strips -> L2 reuse
    int bm = blockIdx.x * 128, bn = blockIdx.y * 128;
    int wid = tid >> 5, lane = tid & 31;
    int wm = (wid & 3) * 32;           // 4 warps along M
    int wn = (wid >> 2) * 32;          // 4 warps along N
    int g  = lane >> 2, tg = lane & 3;

    // cp.async fill mapping: one 16B chunk per thread per array per stage
    int a_row = tid >> 2,  a_col = (tid & 3) * 8;    // A tile 128x32
    int b_row = tid >> 4,  b_col = (tid & 15) * 8;   // B tile 32x128

    unsigned baseAh[NSTAGE], baseAl[NSTAGE], baseBh[NSTAGE], baseBl[NSTAGE];
    #pragma unroll
    for (int s = 0; s < NSTAGE; s++) {
        baseAh[s] = (unsigned)__cvta_generic_to_shared(&Ah[s][0][0]);
        baseAl[s] = (unsigned)__cvta_generic_to_shared(&Al[s][0][0]);
        baseBh[s] = (unsigned)__cvta_generic_to_shared(&Bh[s][0][0]);
        baseBl[s] = (unsigned)__cvta_generic_to_shared(&Bl[s][0][0]);
    }
    unsigned dA = (a_row * SPADA + a_col) * 2;
    unsigned dB = (b_row * SPADB + b_col) * 2;

    auto issue = [&](int s, int k0) {
        cpa16(baseAh[s] + dA, Ah_g + (size_t)(bm + a_row) * K + k0 + a_col);
        cpa16(baseAl[s] + dA, Al_g + (size_t)(bm + a_row) * K + k0 + a_col);
        cpa16(baseBh[s] + dB, Bh_g + (size_t)(k0 + b_row) * N + bn + b_col);
        cpa16(baseBl[s] + dB, Bl_g + (size_t)(k0 + b_row) * N + bn + b_col);
    };

    // ldmatrix lane addressing
    int a_row_l  = wm + (lane & 15);
    int a_col_l  = (lane >> 4) * 8;
    int b_krow_l = lane & 15;
    int b_ncol_l = wn + (lane >> 4) * 8;

    float acc[2][4][4];
    #pragma unroll
    for (int a = 0; a < 2; a++)
        #pragma unroll
        for (int b = 0; b < 4; b++)
            #pragma unroll
            for (int c = 0; c < 4; c++) acc[a][b][c] = 0.f;

    auto compute = [&](int s) {
        #pragma unroll
        for (int kk = 0; kk < BK; kk += 16) {
            unsigned afh[2][4], afl[2][4];
            #pragma unroll
            for (int mt = 0; mt < 2; mt++) {
                unsigned off = ((a_row_l + mt * 16) * SPADA + a_col_l + kk) * 2;
                ldsm4(afh[mt], baseAh[s] + off);
                ldsm4(afl[mt], baseAl[s] + off);
            }
            unsigned bfh[2][4], bfl[2][4];
            #pragma unroll
            for (int p = 0; p < 2; p++) {
                unsigned off = ((kk + b_krow_l) * SPADB + b_ncol_l + p * 16) * 2;
                ldsm4t(bfh[p], baseBh[s] + off);
                ldsm4t(bfl[p], baseBl[s] + off);
            }
            #pragma unroll
            for (int mt = 0; mt < 2; mt++) {
                #pragma unroll
                for (int nt = 0; nt < 4; nt++) {
                    unsigned* bh2 = &bfh[nt >> 1][(nt & 1) * 2];
                    unsigned* bl2 = &bfl[nt >> 1][(nt & 1) * 2];
                    mma16816(acc[mt][nt], afh[mt], bh2);
                    mma16816(acc[mt][nt], afh[mt], bl2);
                    mma16816(acc[mt][nt], afl[mt], bh2);
                }
            }
        }
    };

    // 3-stage pipeline: loads run two chunks ahead, one sync per iteration
    int nchunk = K / BK;
    issue(0, 0);       cpa_commit();
    issue(1, BK);      cpa_commit();
    for (int ch = 0; ch < nchunk; ch++) {
        cpa_wait<1>();
        __syncthreads();
        int nx = ch + 2;
        if (nx < nchunk) issue(nx % NSTAGE, nx * BK);
        cpa_commit();
        compute(ch % NSTAGE);
    }

    // epilogue
    #pragma unroll
    for (int mt = 0; mt < 2; mt++) {
        #pragma unroll
        for (int nt = 0; nt < 4; nt++) {
            int row = bm + wm + mt * 16 + g;
            int col = bn + wn + nt * 8 + tg * 2;
            float2 o0 = make_float2(acc[mt][nt][0], acc[mt][nt][1]);
            float2 o1 = make_float2(acc[mt][nt][2], acc[mt][nt][3]);
            if (EPI >= 1) {
                float2 bb = *(const float2*)(bias + col);
                o0.x += bb.x; o0.y += bb.y; o1.x += bb.x; o1.y += bb.y;
            }
            if (EPI == 3) {
                float2 r0 = *(const float2*)(res + (size_t)row * N + col);
                float2 r1 = *(const float2*)(res + (size_t)(row + 8) * N + col);
                o0.x += r0.x; o0.y += r0.y; o1.x += r1.x; o1.y += r1.y;
            }
            if (EPI == 4) {
                o0.x = fmaxf(o0.x, 0.f); o0.y = fmaxf(o0.y, 0.f);
                o1.x = fmaxf(o1.x, 0.f); o1.y = fmaxf(o1.y, 0.f);
                unsigned h0, l0, h1, l1;
                split2(o0.x, o0.y, h0, l0);
                split2(o1.x, o1.y, h1, l1);
                *(unsigned*)(Chi + (size_t)row * N + col)       = h0;
                *(unsigned*)(Clo + (size_t)row * N + col)       = l0;
                *(unsigned*)(Chi + (size_t)(row + 8) * N + col) = h1;
                *(unsigned*)(Clo + (size_t)(row + 8) * N + col) = l1;
            } else {
                *(float2*)(C + (size_t)row * N + col) = o0;
                *(float2*)(C + (size_t)(row + 8) * N + col) = o1;
            }
        }
    }
}

// ---------------- fused causal GQA attention (fp32 in, bf16-split out) ----------------
__global__ __launch_bounds__(64) void attn_kernel(const float* __restrict__ QKV,
                                                  bf16* __restrict__ Yhi,
                                                  bf16* __restrict__ Ylo) {
    __shared__ __align__(16) float ks[64][64];
    __shared__ __align__(16) float vs[64][64];
    __shared__ float ss[64][65];

    int itile = blockIdx.x;
    int h     = blockIdx.y;
    int b     = blockIdx.z;
    int kvh   = h >> 2;
    int tid   = threadIdx.x;
    int i     = itile * 64 + tid;

    const float scale = 0.125f;
    float q[64], o[64];
    const float* qrow = QKV + ((size_t)(b * SEQ + i)) * QKVD + h * HSZ;
    #pragma unroll
    for (int d = 0; d < 64; d += 4) {
        float4 t = *(const float4*)(qrow + d);
        q[d] = t.x * scale; q[d+1] = t.y * scale; q[d+2] = t.z * scale; q[d+3] = t.w * scale;
    }
    #pragma unroll
    for (int d = 0; d < 64; d++) o[d] = 0.f;
    float m = -1e30f, l = 0.f;

    for (int j0 = 0; j0 <= itile * 64; j0 += 64) {
        const float* krow = QKV + ((size_t)(b * SEQ + j0 + tid)) * QKVD + DIM + kvh * HSZ;
        const float* vrow = krow + KVD;
        #pragma unroll
        for (int d = 0; d < 64; d += 4) {
            *(float4*)&ks[tid][d] = *(const float4*)(krow + d);
            *(float4*)&vs[tid][d] = *(const float4*)(vrow + d);
        }
        __syncthreads();

        float mt = m;
        #pragma unroll 4
        for (int j = 0; j < 64; j++) {
            float acc = 0.f;
            #pragma unroll
            for (int d = 0; d < 64; d += 4) {
                float4 kk = *(const float4*)&ks[j][d];
                acc = fmaf(q[d],   kk.x, acc);
                acc = fmaf(q[d+1], kk.y, acc);
                acc = fmaf(q[d+2], kk.z, acc);
                acc = fmaf(q[d+3], kk.w, acc);
            }
            if (j0 + j > i) acc = -1e30f;
            ss[tid][j] = acc;
            mt = fmaxf(mt, acc);
        }

        float corr = __expf(m - mt);
        l *= corr;
        #pragma unroll
        for (int d = 0; d < 64; d++) o[d] *= corr;

        #pragma unroll 2
        for (int j = 0; j < 64; j++) {
            float p = __expf(ss[tid][j] - mt);
            l += p;
            #pragma unroll
            for (int d = 0; d < 64; d += 4) {
                float4 vv = *(const float4*)&vs[j][d];
                o[d]   = fmaf(p, vv.x, o[d]);
                o[d+1] = fmaf(p, vv.y, o[d+1]);
                o[d+2] = fmaf(p, vv.z, o[d+2]);
                o[d+3] = fmaf(p, vv.w, o[d+3]);
            }
        }
        m = mt;
        __syncthreads();
    }

    float inv = 1.0f / l;
    size_t yo = ((size_t)(b * SEQ + i)) * DIM + h * HSZ;
    #pragma unroll
    for (int d = 0; d < 64; d += 4) {
        uint2 ph, pl;
        split2(o[d] * inv,   o[d+1] * inv, ph.x, pl.x);
        split2(o[d+2] * inv, o[d+3] * inv, ph.y, pl.y);
        *(uint2*)(Yhi + yo + d) = ph;
        *(uint2*)(Ylo + yo + d) = pl;
    }
}

// ---------------- host ----------------
template <typename Tp>
static void* sym_addr(Tp& s) {
    void* p = nullptr;
    cudaGetSymbolAddress(&p, s);
    return p;
}

static void launch_gemm(int epi, const bf16* Ah, const bf16* Al,
                        const bf16* Bh, const bf16* Bl,
                        const float* bias, const float* res,
                        float* C, bf16* Chi, bf16* Clo, int M, int N, int K) {
    dim3 grid(M / 128, N / 128);   // M-fastest
    switch (epi) {
        case 0: gemm_bf<0><<<grid, 512>>>(Ah, Al, Bh, Bl, bias, res, C, Chi, Clo, M, N, K); break;
        case 1: gemm_bf<1><<<grid, 512>>>(Ah, Al, Bh, Bl, bias, res, C, Chi, Clo, M, N, K); break;
        case 3: gemm_bf<3><<<grid, 512>>>(Ah, Al, Bh, Bl, bias, res, C, Chi, Clo, M, N, K); break;
        case 4: gemm_bf<4><<<grid, 512>>>(Ah, Al, Bh, Bl, bias, res, C, Chi, Clo, M, N, K); break;
    }
}

extern "C" void kernel_launch(void* const* d_in, const int* in_sizes, int n_in,
                              void* d_out, int out_size) {
    const int*   tok   = (const int*)  d_in[0];
    const float* te    = (const float*)d_in[1];
    const float* pe    = (const float*)d_in[2];
    const float* ln1g  = (const float*)d_in[3];
    const float* ln1b  = (const float*)d_in[4];
    const float* Wq    = (const float*)d_in[5];
    const float* Wk    = (const float*)d_in[6];
    const float* Wv    = (const float*)d_in[7];
    const float* Wo    = (const float*)d_in[8];
    const float* bo    = (const float*)d_in[9];
    const float* ln2g  = (const float*)d_in[10];
    const float* ln2b  = (const float*)d_in[11];
    const float* W1    = (const float*)d_in[12];
    const float* b1    = (const float*)d_in[13];
    const float* W2    = (const float*)d_in[14];
    const float* b2    = (const float*)d_in[15];
    const float* lnfg  = (const float*)d_in[16];
    const float* lnfb  = (const float*)d_in[17];
    const float* Wlm   = (const float*)d_in[18];
    const float* blm   = (const float*)d_in[19];
    float* out = (float*)d_out;

    float* x    = (float*)sym_addr(g_x);
    float* qkv  = (float*)sym_addr(g_qkv);
    bf16* h_hi  = (bf16*)sym_addr(g_h_hi),  * h_lo  = (bf16*)sym_addr(g_h_lo);
    bf16* y_hi  = (bf16*)sym_addr(g_y_hi),  * y_lo  = (bf16*)sym_addr(g_y_lo);
    bf16* ff_hi = (bf16*)sym_addr(g_ff_hi), * ff_lo = (bf16*)sym_addr(g_ff_lo);
    bf16* wqkv_hi = (bf16*)sym_addr(g_wqkv_hi), * wqkv_lo = (bf16*)sym_addr(g_wqkv_lo);
    bf16* wo_hi   = (bf16*)sym_addr(g_wo_hi),   * wo_lo   = (bf16*)sym_addr(g_wo_lo);
    bf16* w1_hi   = (bf16*)sym_addr(g_w1_hi),   * w1_lo   = (bf16*)sym_addr(g_w1_lo);
    bf16* w2_hi   = (bf16*)sym_addr(g_w2_hi),   * w2_lo   = (bf16*)sym_addr(g_w2_lo);
    bf16* wlm_hi  = (bf16*)sym_addr(g_wlm_hi),  * wlm_lo  = (bf16*)sym_addr(g_wlm_lo);

    // --- weight pre-split (once per pass) ---
    {
        int n4;
        n4 = NLAYER * DIM * (QKVD / 4);
        concat_split_qkv<<<(n4 + 255) / 256, 256>>>(Wq, Wk, Wv, wqkv_hi, wqkv_lo);
        n4 = NLAYER * DIM * DIM / 4;
        split_kernel<<<(n4 + 255) / 256, 256>>>(Wo, wo_hi, wo_lo, n4);
        n4 = NLAYER * DIM * FFD / 4;
        split_kernel<<<(n4 + 255) / 256, 256>>>(W1, w1_hi, w1_lo, n4);
        n4 = NLAYER * FFD * DIM / 4;
        split_kernel<<<(n4 + 255) / 256, 256>>>(W2, w2_hi, w2_lo, n4);
        n4 = DIM * VOCAB / 4;
        split_kernel<<<(n4 + 255) / 256, 256>>>(Wlm, wlm_hi, wlm_lo, n4);
    }

    embed_kernel<<<NTOK * DIM / 256, 256>>>(tok, te, pe, x);

    for (int l = 0; l < NLAYER; l++) {
        const bf16* wqh = wqkv_hi + (size_t)l * DIM * QKVD;
        const bf16* wql = wqkv_lo + (size_t)l * DIM * QKVD;
        const bf16* woh = wo_hi   + (size_t)l * DIM * DIM;
        const bf16* wol = wo_lo   + (size_t)l * DIM * DIM;
        const bf16* w1h = w1_hi   + (size_t)l * DIM * FFD;
        const bf16* w1l = w1_lo   + (size_t)l * DIM * FFD;
        const bf16* w2h = w2_hi   + (size_t)l * FFD * DIM;
        const bf16* w2l = w2_lo   + (size_t)l * FFD * DIM;

        ln_kernel<<<NTOK, 256>>>(x, ln1g + l * DIM, ln1b + l * DIM, h_hi, h_lo);

        launch_gemm(0, h_hi, h_lo, wqh, wql, nullptr, nullptr, qkv, nullptr, nullptr,
                    NTOK, QKVD, DIM);

        attn_kernel<<<dim3(SEQ / 64, NH, NB), 64>>>(qkv, y_hi, y_lo);

        launch_gemm(3, y_hi, y_lo, woh, wol, bo + l * DIM, x, x, nullptr, nullptr,
                    NTOK, DIM, DIM);

        ln_kernel<<<NTOK, 256>>>(x, ln2g + l * DIM, ln2b + l * DIM, h_hi, h_lo);

        launch_gemm(4, h_hi, h_lo, w1h, w1l, b1 + (size_t)l * FFD, nullptr,
                    nullptr, ff_hi, ff_lo, NTOK, FFD, DIM);
        launch_gemm(3, ff_hi, ff_lo, w2h, w2l, b2 + l * DIM, x, x, nullptr, nullptr,
                    NTOK, DIM, FFD);
    }

    ln_kernel<<<NTOK, 256>>>(x, lnfg, lnfb, h_hi, h_lo);
    launch_gemm(1, h_hi, h_lo, wlm_hi, wlm_lo, blm, nullptr, out, nullptr, nullptr,
                NTOK, VOCAB, DIM);
}

// round 15
// speedup vs baseline: 1.0677x; 1.0677x over previous
#include <cuda_runtime.h>
#include <cuda_bf16.h>

// ---------------- problem dims ----------------
#define NB     2
#define SEQ    1024
#define DIM    1024
#define NH     16
#define NKV    4
#define HSZ    64
#define NLAYER 6
#define VOCAB  32000
#define FFD    4096
#define NTOK   (NB*SEQ)          // 2048
#define KVD    (NKV*HSZ)         // 256
#define QKVD   (DIM + 2*KVD)     // 1536

typedef __nv_bfloat16 bf16;

// ---------------- scratch (256B-aligned) ----------------
__device__ __align__(256) float g_x  [NTOK*DIM];
__device__ __align__(256) float g_qkv[NTOK*QKVD];
__device__ __align__(256) bf16 g_h_hi [NTOK*DIM];
__device__ __align__(256) bf16 g_h_lo [NTOK*DIM];
__device__ __align__(256) bf16 g_y_hi [NTOK*DIM];
__device__ __align__(256) bf16 g_y_lo [NTOK*DIM];
__device__ __align__(256) bf16 g_ff_hi[NTOK*FFD];
__device__ __align__(256) bf16 g_ff_lo[NTOK*FFD];
__device__ __align__(256) bf16 g_wqkv_hi[NLAYER*DIM*QKVD];
__device__ __align__(256) bf16 g_wqkv_lo[NLAYER*DIM*QKVD];
__device__ __align__(256) bf16 g_wo_hi  [NLAYER*DIM*DIM];
__device__ __align__(256) bf16 g_wo_lo  [NLAYER*DIM*DIM];
__device__ __align__(256) bf16 g_w1_hi  [NLAYER*DIM*FFD];
__device__ __align__(256) bf16 g_w1_lo  [NLAYER*DIM*FFD];
__device__ __align__(256) bf16 g_w2_hi  [NLAYER*FFD*DIM];
__device__ __align__(256) bf16 g_w2_lo  [NLAYER*FFD*DIM];
__device__ __align__(256) bf16 g_wlm_hi [DIM*VOCAB];
__device__ __align__(256) bf16 g_wlm_lo [DIM*VOCAB];

// ---------------- helpers ----------------
__device__ __forceinline__ unsigned packbf2(float a, float b) {
    __nv_bfloat162 t = __floats2bfloat162_rn(a, b);
    return *(unsigned*)&t;
}
__device__ __forceinline__ void split2(float a, float b, unsigned& hi, unsigned& lo) {
    bf16 ha = __float2bfloat16(a), hb = __float2bfloat16(b);
    float la = a - __bfloat162float(ha);
    float lb = b - __bfloat162float(hb);
    __nv_bfloat162 h2 = __halves2bfloat162(ha, hb);
    hi = *(unsigned*)&h2;
    lo = packbf2(la, lb);
}

// ---------------- embedding ----------------
__global__ void embed_kernel(const int* __restrict__ tok, const float* __restrict__ te,
                             const float* __restrict__ pe, float* __restrict__ x) {
    int idx = blockIdx.x * 256 + threadIdx.x;
    int row = idx >> 10;
    int d   = idx & (DIM - 1);
    int t   = row & (SEQ - 1);
    x[idx] = te[(size_t)tok[row] * DIM + d] + pe[t * DIM + d];
}

// ---------------- split fp32 -> bf16 hi/lo (bulk, float4) ----------------
__global__ void split_kernel(const float* __restrict__ src, bf16* __restrict__ hi,
                             bf16* __restrict__ lo, int n4) {
    int i = blockIdx.x * 256 + threadIdx.x;
    if (i >= n4) return;
    float4 v = ((const float4*)src)[i];
    uint2 ph, pl;
    split2(v.x, v.y, ph.x, pl.x);
    split2(v.z, v.w, ph.y, pl.y);
    ((uint2*)hi)[i] = ph;
    ((uint2*)lo)[i] = pl;
}

// ---------------- concat Wq|Wk|Wv (all layers) + split ----------------
__global__ void concat_split_qkv(const float* __restrict__ Wq, const float* __restrict__ Wk,
                                 const float* __restrict__ Wv,
                                 bf16* __restrict__ hi, bf16* __restrict__ lo) {
    int idx4 = blockIdx.x * 256 + threadIdx.x;
    if (idx4 >= NLAYER * DIM * (QKVD / 4)) return;
    int l   = idx4 / (DIM * (QKVD / 4));
    int r   = idx4 % (DIM * (QKVD / 4));
    int row = r / (QKVD / 4);
    int col = (r % (QKVD / 4)) * 4;
    float4 v;
    if (col < DIM)            v = *(const float4*)(Wq + ((size_t)l * DIM + row) * DIM + col);
    else if (col < DIM + KVD) v = *(const float4*)(Wk + ((size_t)l * DIM + row) * KVD + (col - DIM));
    else                      v = *(const float4*)(Wv + ((size_t)l * DIM + row) * KVD + (col - DIM - KVD));
    uint2 ph, pl;
    split2(v.x, v.y, ph.x, pl.x);
    split2(v.z, v.w, ph.y, pl.y);
    size_t o = ((size_t)l * DIM + row) * QKVD + col;
    *(uint2*)(hi + o) = ph;
    *(uint2*)(lo + o) = pl;
}

// ---------------- layernorm -> split bf16 hi/lo ----------------
__global__ __launch_bounds__(256) void ln_kernel(const float* __restrict__ x,
                                                 const float* __restrict__ g,
                                                 const float* __restrict__ b,
                                                 bf16* __restrict__ yhi,
                                                 bf16* __restrict__ ylo) {
    int row = blockIdx.x;
    int tid = threadIdx.x;
    const float* xr = x + (size_t)row * DIM;
    float4 v = *(const float4*)(xr + tid * 4);
    float sum = v.x + v.y + v.z + v.w;
    float sq  = v.x*v.x + v.y*v.y + v.z*v.z + v.w*v.w;
    #pragma unroll
    for (int o = 16; o > 0; o >>= 1) {
        sum += __shfl_xor_sync(0xffffffffu, sum, o);
        sq  += __shfl_xor_sync(0xffffffffu, sq,  o);
    }
    __shared__ float sh[18];
    int wid = tid >> 5, lane = tid & 31;
    if (lane == 0) { sh[wid] = sum; sh[8 + wid] = sq; }
    __syncthreads();
    if (tid == 0) {
        float a = 0.f, c = 0.f;
        #pragma unroll
        for (int w = 0; w < 8; w++) { a += sh[w]; c += sh[8 + w]; }
        float mu  = a * (1.0f / DIM);
        float var = c * (1.0f / DIM) - mu * mu;
        sh[16] = mu;
        sh[17] = rsqrtf(var + 1e-5f);
    }
    __syncthreads();
    float mu = sh[16], rstd = sh[17];
    float4 gg = *(const float4*)(g + tid * 4);
    float4 bb = *(const float4*)(b + tid * 4);
    float o0 = (v.x - mu) * rstd * gg.x + bb.x;
    float o1 = (v.y - mu) * rstd * gg.y + bb.y;
    float o2 = (v.z - mu) * rstd * gg.z + bb.z;
    float o3 = (v.w - mu) * rstd * gg.w + bb.w;
    uint2 ph, pl;
    split2(o0, o1, ph.x, pl.x);
    split2(o2, o3, ph.y, pl.y);
    *(uint2*)(yhi + (size_t)row * DIM + tid * 4) = ph;
    *(uint2*)(ylo + (size_t)row * DIM + tid * 4) = pl;
}

// =====================================================================
// bf16 split-GEMM — R12 config (best): 256 threads / 8 warps
// (2M x 4N, 64x32 warp tiles), BK=64, 3-stage cp.async, M-fastest grid.
// C = (Ah+Al)(MxK) @ (Bh+Bl)(KxN), 3-term fp32 acc.
// EPI: 0 plain, 1 +bias, 3 +bias+res, 4 +bias+relu -> bf16 hi/lo
// =====================================================================
#define BK     64
#define SPADA  72
#define SPADB  136
#define NSTAGE 3

__device__ __forceinline__ void mma16816(float* c, const unsigned* a, const unsigned* b) {
    asm volatile(
        "mma.sync.aligned.m16n8k16.row.col.f32.bf16.bf16.f32 "
        "{%0,%1,%2,%3}, {%4,%5,%6,%7}, {%8,%9}, {%0,%1,%2,%3};\n"
        : "+f"(c[0]), "+f"(c[1]), "+f"(c[2]), "+f"(c[3])
        : "r"(a[0]), "r"(a[1]), "r"(a[2]), "r"(a[3]), "r"(b[0]), "r"(b[1]));
}
__device__ __forceinline__ void ldsm4(unsigned* r, unsigned addr) {
    asm volatile("ldmatrix.sync.aligned.m8n8.x4.shared.b16 {%0,%1,%2,%3}, [%4];\n"
                 : "=r"(r[0]), "=r"(r[1]), "=r"(r[2]), "=r"(r[3]) : "r"(addr));
}
__device__ __forceinline__ void ldsm4t(unsigned* r, unsigned addr) {
    asm volatile("ldmatrix.sync.aligned.m8n8.x4.trans.shared.b16 {%0,%1,%2,%3}, [%4];\n"
                 : "=r"(r[0]), "=r"(r[1]), "=r"(r[2]), "=r"(r[3]) : "r"(addr));
}
__device__ __forceinline__ void cpa16(unsigned dst, const void* src) {
    asm volatile("cp.async.cg.shared.global [%0], [%1], 16;\n" :: "r"(dst), "l"(src) : "memory");
}
__device__ __forceinline__ void cpa_commit() {
    asm volatile("cp.async.commit_group;\n" ::: "memory");
}
template <int Npend>
__device__ __forceinline__ void cpa_wait() {
    asm volatile("cp.async.wait_group %0;\n" :: "n"(Npend) : "memory");
}

template <int EPI>
__global__ __launch_bounds__(256, 1) void gemm_bf(const bf16* __restrict__ Ah_g,
                                                  const bf16* __restrict__ Al_g,
                                                  const bf16* __restrict__ Bh_g,
                                                  const bf16* __restrict__ Bl_g,
                                                  const float* __restrict__ bias,
                                                  const float* __restrict__ res,
                                                  float* __restrict__ C,
                                                  bf16* __restrict__ Chi,
                                                  bf16* __restrict__ Clo,
                                                  int M, int N, int K) {
    __shared__ __align__(16) bf16 Ah[NSTAGE][128][SPADA], Al[NSTAGE][128][SPADA];
    __shared__ __align__(16) bf16 Bh[NSTAGE][BK][SPADB],  Bl[NSTAGE][BK][SPADB];

    int tid = threadIdx.x;
    int bm = blockIdx.x * 128, bn = blockIdx.y * 128;   // M-fastest
    int wid = tid >> 5, lane = tid & 31;
    int wm = (wid & 1) * 64;
    int wn = (wid >> 1) * 32;
    int g  = lane >> 2, tg = lane & 3;

    int a_row[4], a_col[4], b_row[4], b_col[4];
    #pragma unroll
    for (int i = 0; i < 4; i++) {
        int idx = tid + i * 256;
        a_row[i] = idx >> 3;  a_col[i] = (idx & 7) * 8;
        b_row[i] = idx >> 4;  b_col[i] = (idx & 15) * 8;
    }

    unsigned baseAh[NSTAGE], baseAl[NSTAGE], baseBh[NSTAGE], baseBl[NSTAGE];
    #pragma unroll
    for (int s = 0; s < NSTAGE; s++) {
        baseAh[s] = (unsigned)__cvta_generic_to_shared(&Ah[s][0][0]);
        baseAl[s] = (unsigned)__cvta_generic_to_shared(&Al[s][0][0]);
        baseBh[s] = (unsigned)__cvta_generic_to_shared(&Bh[s][0][0]);
        baseBl[s] = (unsigned)__cvta_generic_to_shared(&Bl[s][0][0]);
    }
    unsigned dA[4], dB[4];
    #pragma unroll
    for (int i = 0; i < 4; i++) {
        dA[i] = (a_row[i] * SPADA + a_col[i]) * 2;
        dB[i] = (b_row[i] * SPADB + b_col[i]) * 2;
    }

    auto issue = [&](int s, int k0) {
        #pragma unroll
        for (int i = 0; i < 4; i++) {
            size_t ao = (size_t)(bm + a_row[i]) * K + k0 + a_col[i];
            size_t bo = (size_t)(k0 + b_row[i]) * N + bn + b_col[i];
            cpa16(baseAh[s] + dA[i], Ah_g + ao);
            cpa16(baseAl[s] + dA[i], Al_g + ao);
            cpa16(baseBh[s] + dB[i], Bh_g + bo);
            cpa16(baseBl[s] + dB[i], Bl_g + bo);
        }
    };

    int a_row_l  = wm + (lane & 15);
    int a_col_l  = (lane >> 4) * 8;
    int b_krow_l = lane & 15;
    int b_ncol_l = wn + (lane >> 4) * 8;

    float acc[4][4][4];
    #pragma unroll
    for (int a = 0; a < 4; a++)
        #pragma unroll
        for (int b = 0; b < 4; b++)
            #pragma unroll
            for (int c = 0; c < 4; c++) acc[a][b][c] = 0.f;

    auto compute = [&](int s) {
        #pragma unroll
        for (int kk = 0; kk < BK; kk += 16) {
            unsigned afh[4][4], afl[4][4];
            #pragma unroll
            for (int mt = 0; mt < 4; mt++) {
                unsigned off = ((a_row_l + mt * 16) * SPADA + a_col_l + kk) * 2;
                ldsm4(afh[mt], baseAh[s] + off);
                ldsm4(afl[mt], baseAl[s] + off);
            }
            unsigned bfh[2][4], bfl[2][4];
            #pragma unroll
            for (int p = 0; p < 2; p++) {
                unsigned off = ((kk + b_krow_l) * SPADB + b_ncol_l + p * 16) * 2;
                ldsm4t(bfh[p], baseBh[s] + off);
                ldsm4t(bfl[p], baseBl[s] + off);
            }
            #pragma unroll
            for (int mt = 0; mt < 4; mt++) {
                #pragma unroll
                for (int nt = 0; nt < 4; nt++) {
                    unsigned* bh2 = &bfh[nt >> 1][(nt & 1) * 2];
                    unsigned* bl2 = &bfl[nt >> 1][(nt & 1) * 2];
                    mma16816(acc[mt][nt], afh[mt], bh2);
                    mma16816(acc[mt][nt], afh[mt], bl2);
                    mma16816(acc[mt][nt], afl[mt], bh2);
                }
            }
        }
    };

    int nchunk = K / BK;
    issue(0, 0);       cpa_commit();
    issue(1, BK);      cpa_commit();
    for (int ch = 0; ch < nchunk; ch++) {
        cpa_wait<1>();
        __syncthreads();
        int nx = ch + 2;
        if (nx < nchunk) issue(nx % NSTAGE, nx * BK);
        cpa_commit();
        compute(ch % NSTAGE);
    }

    #pragma unroll
    for (int mt = 0; mt < 4; mt++) {
        #pragma unroll
        for (int nt = 0; nt < 4; nt++) {
            int row = bm + wm + mt * 16 + g;
            int col = bn + wn + nt * 8 + tg * 2;
            float2 o0 = make_float2(acc[mt][nt][0], acc[mt][nt][1]);
            float2 o1 = make_float2(acc[mt][nt][2], acc[mt][nt][3]);
            if (EPI >= 1) {
                float2 bb = *(const float2*)(bias + col);
                o0.x += bb.x; o0.y += bb.y; o1.x += bb.x; o1.y += bb.y;
            }
            if (EPI == 3) {
                float2 r0 = *(const float2*)(res + (size_t)row * N + col);
                float2 r1 = *(const float2*)(res + (size_t)(row + 8) * N + col);
                o0.x += r0.x; o0.y += r0.y; o1.x += r1.x; o1.y += r1.y;
            }
            if (EPI == 4) {
                o0.x = fmaxf(o0.x, 0.f); o0.y = fmaxf(o0.y, 0.f);
                o1.x = fmaxf(o1.x, 0.f); o1.y = fmaxf(o1.y, 0.f);
                unsigned h0, l0, h1, l1;
                split2(o0.x, o0.y, h0, l0);
                split2(o1.x, o1.y, h1, l1);
                *(unsigned*)(Chi + (size_t)row * N + col)       = h0;
                *(unsigned*)(Clo + (size_t)row * N + col)       = l0;
                *(unsigned*)(Chi + (size_t)(row + 8) * N + col) = h1;
                *(unsigned*)(Clo + (size_t)(row + 8) * N + col) = l1;
            } else {
                *(float2*)(C + (size_t)row * N + col) = o0;
                *(float2*)(C + (size_t)(row + 8) * N + col) = o1;
            }
        }
    }
}

// ---------------- fused causal GQA attention (fp32 in, bf16-split out) ----------------
__global__ __launch_bounds__(64) void attn_kernel(const float* __restrict__ QKV,
                                                  bf16* __restrict__ Yhi,
                                                  bf16* __restrict__ Ylo) {
    __shared__ __align__(16) float ks[64][64];
    __shared__ __align__(16) float vs[64][64];
    __shared__ float ss[64][65];

    int itile = blockIdx.x;
    int h     = blockIdx.y;
    int b     = blockIdx.z;
    int kvh   = h >> 2;
    int tid   = threadIdx.x;
    int i     = itile * 64 + tid;

    const float scale = 0.125f;
    float q[64], o[64];
    const float* qrow = QKV + ((size_t)(b * SEQ + i)) * QKVD + h * HSZ;
    #pragma unroll
    for (int d = 0; d < 64; d += 4) {
        float4 t = *(const float4*)(qrow + d);
        q[d] = t.x * scale; q[d+1] = t.y * scale; q[d+2] = t.z * scale; q[d+3] = t.w * scale;
    }
    #pragma unroll
    for (int d = 0; d < 64; d++) o[d] = 0.f;
    float m = -1e30f, l = 0.f;

    for (int j0 = 0; j0 <= itile * 64; j0 += 64) {
        const float* krow = QKV + ((size_t)(b * SEQ + j0 + tid)) * QKVD + DIM + kvh * HSZ;
        const float* vrow = krow + KVD;
        #pragma unroll
        for (int d = 0; d < 64; d += 4) {
            *(float4*)&ks[tid][d] = *(const float4*)(krow + d);
            *(float4*)&vs[tid][d] = *(const float4*)(vrow + d);
        }
        __syncthreads();

        float mt = m;
        #pragma unroll 4
        for (int j = 0; j < 64; j++) {
            float acc = 0.f;
            #pragma unroll
            for (int d = 0; d < 64; d += 4) {
                float4 kk = *(const float4*)&ks[j][d];
                acc = fmaf(q[d],   kk.x, acc);
                acc = fmaf(q[d+1], kk.y, acc);
                acc = fmaf(q[d+2], kk.z, acc);
                acc = fmaf(q[d+3], kk.w, acc);
            }
            if (j0 + j > i) acc = -1e30f;
            ss[tid][j] = acc;
            mt = fmaxf(mt, acc);
        }

        float corr = __expf(m - mt);
        l *= corr;
        #pragma unroll
        for (int d = 0; d < 64; d++) o[d] *= corr;

        #pragma unroll 2
        for (int j = 0; j < 64; j++) {
            float p = __expf(ss[tid][j] - mt);
            l += p;
            #pragma unroll
            for (int d = 0; d < 64; d += 4) {
                float4 vv = *(const float4*)&vs[j][d];
                o[d]   = fmaf(p, vv.x, o[d]);
                o[d+1] = fmaf(p, vv.y, o[d+1]);
                o[d+2] = fmaf(p, vv.z, o[d+2]);
                o[d+3] = fmaf(p, vv.w, o[d+3]);
            }
        }
        m = mt;
        __syncthreads();
    }

    float inv = 1.0f / l;
    size_t yo = ((size_t)(b * SEQ + i)) * DIM + h * HSZ;
    #pragma unroll
    for (int d = 0; d < 64; d += 4) {
        uint2 ph, pl;
        split2(o[d] * inv,   o[d+1] * inv, ph.x, pl.x);
        split2(o[d+2] * inv, o[d+3] * inv, ph.y, pl.y);
        *(uint2*)(Yhi + yo + d) = ph;
        *(uint2*)(Ylo + yo + d) = pl;
    }
}

// ---------------- host ----------------
template <typename Tp>
static void* sym_addr(Tp& s) {
    void* p = nullptr;
    cudaGetSymbolAddress(&p, s);
    return p;
}

static void launch_gemm(int epi, const bf16* Ah, const bf16* Al,
                        const bf16* Bh, const bf16* Bl,
                        const float* bias, const float* res,
                        float* C, bf16* Chi, bf16* Clo, int M, int N, int K) {
    dim3 grid(M / 128, N / 128);   // M-fastest
    switch (epi) {
        case 0: gemm_bf<0><<<grid, 256>>>(Ah, Al, Bh, Bl, bias, res, C, Chi, Clo, M, N, K); break;
        case 1: gemm_bf<1><<<grid, 256>>>(Ah, Al, Bh, Bl, bias, res, C, Chi, Clo, M, N, K); break;
        case 3: gemm_bf<3><<<grid, 256>>>(Ah, Al, Bh, Bl, bias, res, C, Chi, Clo, M, N, K); break;
        case 4: gemm_bf<4><<<grid, 256>>>(Ah, Al, Bh, Bl, bias, res, C, Chi, Clo, M, N, K); break;
    }
}

extern "C" void kernel_launch(void* const* d_in, const int* in_sizes, int n_in,
                              void* d_out, int out_size) {
    const int*   tok   = (const int*)  d_in[0];
    const float* te    = (const float*)d_in[1];
    const float* pe    = (const float*)d_in[2];
    const float* ln1g  = (const float*)d_in[3];
    const float* ln1b  = (const float*)d_in[4];
    const float* Wq    = (const float*)d_in[5];
    const float* Wk    = (const float*)d_in[6];
    const float* Wv    = (const float*)d_in[7];
    const float* Wo    = (const float*)d_in[8];
    const float* bo    = (const float*)d_in[9];
    const float* ln2g  = (const float*)d_in[10];
    const float* ln2b  = (const float*)d_in[11];
    const float* W1    = (const float*)d_in[12];
    const float* b1    = (const float*)d_in[13];
    const float* W2    = (const float*)d_in[14];
    const float* b2    = (const float*)d_in[15];
    const float* lnfg  = (const float*)d_in[16];
    const float* lnfb  = (const float*)d_in[17];
    const float* Wlm   = (const float*)d_in[18];
    const float* blm   = (const float*)d_in[19];
    float* out = (float*)d_out;

    float* x    = (float*)sym_addr(g_x);
    float* qkv  = (float*)sym_addr(g_qkv);
    bf16* h_hi  = (bf16*)sym_addr(g_h_hi),  * h_lo  = (bf16*)sym_addr(g_h_lo);
    bf16* y_hi  = (bf16*)sym_addr(g_y_hi),  * y_lo  = (bf16*)sym_addr(g_y_lo);
    bf16* ff_hi = (bf16*)sym_addr(g_ff_hi), * ff_lo = (bf16*)sym_addr(g_ff_lo);
    bf16* wqkv_hi = (bf16*)sym_addr(g_wqkv_hi), * wqkv_lo = (bf16*)sym_addr(g_wqkv_lo);
    bf16* wo_hi   = (bf16*)sym_addr(g_wo_hi),   * wo_lo   = (bf16*)sym_addr(g_wo_lo);
    bf16* w1_hi   = (bf16*)sym_addr(g_w1_hi),   * w1_lo   = (bf16*)sym_addr(g_w1_lo);
    bf16* w2_hi   = (bf16*)sym_addr(g_w2_hi),   * w2_lo   = (bf16*)sym_addr(g_w2_lo);
    bf16* wlm_hi  = (bf16*)sym_addr(g_wlm_hi),  * wlm_lo  = (bf16*)sym_addr(g_wlm_lo);

    // side stream for weight pre-split (created per-call; capture runs this
    // host code exactly once, replays execute only the recorded graph)
    cudaStream_t s2;
    cudaEvent_t evFork, evJoin;
    cudaStreamCreateWithFlags(&s2, cudaStreamNonBlocking);
    cudaEventCreateWithFlags(&evFork, cudaEventDisableTiming);
    cudaEventCreateWithFlags(&evJoin, cudaEventDisableTiming);

    // main stream: qkv weights (needed first) + embed
    {
        int n4 = NLAYER * DIM * (QKVD / 4);
        concat_split_qkv<<<(n4 + 255) / 256, 256>>>(Wq, Wk, Wv, wqkv_hi, wqkv_lo);
    }
    embed_kernel<<<NTOK * DIM / 256, 256>>>(tok, te, pe, x);

    // fork: remaining weight splits run on s2, overlapping qkv GEMM + attention
    cudaEventRecord(evFork, 0);
    cudaStreamWaitEvent(s2, evFork, 0);
    {
        int n4;
        n4 = NLAYER * DIM * DIM / 4;
        split_kernel<<<(n4 + 255) / 256, 256, 0, s2>>>(Wo, wo_hi, wo_lo, n4);
        n4 = NLAYER * DIM * FFD / 4;
        split_kernel<<<(n4 + 255) / 256, 256, 0, s2>>>(W1, w1_hi, w1_lo, n4);
        n4 = NLAYER * FFD * DIM / 4;
        split_kernel<<<(n4 + 255) / 256, 256, 0, s2>>>(W2, w2_hi, w2_lo, n4);
        n4 = DIM * VOCAB / 4;
        split_kernel<<<(n4 + 255) / 256, 256, 0, s2>>>(Wlm, wlm_hi, wlm_lo, n4);
    }
    cudaEventRecord(evJoin, s2);

    bool joined = false;
    for (int l = 0; l < NLAYER; l++) {
        const bf16* wqh = wqkv_hi + (size_t)l * DIM * QKVD;
        const bf16* wql = wqkv_lo + (size_t)l * DIM * QKVD;
        const bf16* woh = wo_hi   + (size_t)l * DIM * DIM;
        const bf16* wol = wo_lo   + (size_t)l * DIM * DIM;
        const bf16* w1h = w1_hi   + (size_t)l * DIM * FFD;
        const bf16* w1l = w1_lo   + (size_t)l * DIM * FFD;
        const bf16* w2h = w2_hi   + (size_t)l * FFD * DIM;
        const bf16* w2l = w2_lo   + (size_t)l * FFD * DIM;

        ln_kernel<<<NTOK, 256>>>(x, ln1g + l * DIM, ln1b + l * DIM, h_hi, h_lo);

        launch_gemm(0, h_hi, h_lo, wqh, wql, nullptr, nullptr, qkv, nullptr, nullptr,
                    NTOK, QKVD, DIM);

        attn_kernel<<<dim3(SEQ / 64, NH, NB), 64>>>(qkv, y_hi, y_lo);

        // join before first use of wo/w1/w2 splits
        if (!joined) { cudaStreamWaitEvent(0, evJoin, 0); joined = true; }

        launch_gemm(3, y_hi, y_lo, woh, wol, bo + l * DIM, x, x, nullptr, nullptr,
                    NTOK, DIM, DIM);

        ln_kernel<<<NTOK, 256>>>(x, ln2g + l * DIM, ln2b + l * DIM, h_hi, h_lo);

        launch_gemm(4, h_hi, h_lo, w1h, w1l, b1 + (size_t)l * FFD, nullptr,
                    nullptr, ff_hi, ff_lo, NTOK, FFD, DIM);
        launch_gemm(3, ff_hi, ff_lo, w2h, w2l, b2 + l * DIM, x, x, nullptr, nullptr,
                    NTOK, DIM, FFD);
    }

    ln_kernel<<<NTOK, 256>>>(x, lnfg, lnfb, h_hi, h_lo);
    launch_gemm(1, h_hi, h_lo, wlm_hi, wlm_lo, blm, nullptr, out, nullptr, nullptr,
                NTOK, VOCAB, DIM);

    // release per-call handles (host-side objects; no device memory)
    cudaEventDestroy(evFork);
    cudaEventDestroy(evJoin);
    cudaStreamDestroy(s2);
}

// round 16
// speedup vs baseline: 1.2014x; 1.1252x over previous
#include <cuda_runtime.h>
#include <cuda_bf16.h>

// ---------------- problem dims ----------------
#define NB     2
#define SEQ    1024
#define DIM    1024
#define NH     16
#define NKV    4
#define HSZ    64
#define NLAYER 6
#define VOCAB  32000
#define FFD    4096
#define NTOK   (NB*SEQ)          // 2048
#define KVD    (NKV*HSZ)         // 256
#define QKVD   (DIM + 2*KVD)     // 1536

typedef __nv_bfloat16 bf16;

// ---------------- scratch (256B-aligned) ----------------
__device__ __align__(256) float g_x  [NTOK*DIM];
__device__ __align__(256) float g_qkv[NTOK*QKVD];
__device__ __align__(256) bf16 g_h_hi [NTOK*DIM];
__device__ __align__(256) bf16 g_h_lo [NTOK*DIM];
__device__ __align__(256) bf16 g_y_hi [NTOK*DIM];
__device__ __align__(256) bf16 g_y_lo [NTOK*DIM];
__device__ __align__(256) bf16 g_ff_hi[NTOK*FFD];
__device__ __align__(256) bf16 g_ff_lo[NTOK*FFD];
__device__ __align__(256) bf16 g_wqkv_hi[NLAYER*DIM*QKVD];
__device__ __align__(256) bf16 g_wqkv_lo[NLAYER*DIM*QKVD];
__device__ __align__(256) bf16 g_wo_hi  [NLAYER*DIM*DIM];
__device__ __align__(256) bf16 g_wo_lo  [NLAYER*DIM*DIM];
__device__ __align__(256) bf16 g_w1_hi  [NLAYER*DIM*FFD];
__device__ __align__(256) bf16 g_w1_lo  [NLAYER*DIM*FFD];
__device__ __align__(256) bf16 g_w2_hi  [NLAYER*FFD*DIM];
__device__ __align__(256) bf16 g_w2_lo  [NLAYER*FFD*DIM];
__device__ __align__(256) bf16 g_wlm_hi [DIM*VOCAB];
__device__ __align__(256) bf16 g_wlm_lo [DIM*VOCAB];

// ---------------- helpers ----------------
__device__ __forceinline__ unsigned packbf2(float a, float b) {
    __nv_bfloat162 t = __floats2bfloat162_rn(a, b);
    return *(unsigned*)&t;
}
__device__ __forceinline__ void split2(float a, float b, unsigned& hi, unsigned& lo) {
    bf16 ha = __float2bfloat16(a), hb = __float2bfloat16(b);
    float la = a - __bfloat162float(ha);
    float lb = b - __bfloat162float(hb);
    __nv_bfloat162 h2 = __halves2bfloat162(ha, hb);
    hi = *(unsigned*)&h2;
    lo = packbf2(la, lb);
}

// ---------------- embedding ----------------
__global__ void embed_kernel(const int* __restrict__ tok, const float* __restrict__ te,
                             const float* __restrict__ pe, float* __restrict__ x) {
    int idx = blockIdx.x * 256 + threadIdx.x;
    int row = idx >> 10;
    int d   = idx & (DIM - 1);
    int t   = row & (SEQ - 1);
    x[idx] = te[(size_t)tok[row] * DIM + d] + pe[t * DIM + d];
}

// ---------------- split fp32 -> bf16 hi/lo (bulk, float4) ----------------
__global__ void split_kernel(const float* __restrict__ src, bf16* __restrict__ hi,
                             bf16* __restrict__ lo, int n4) {
    int i = blockIdx.x * 256 + threadIdx.x;
    if (i >= n4) return;
    float4 v = ((const float4*)src)[i];
    uint2 ph, pl;
    split2(v.x, v.y, ph.x, pl.x);
    split2(v.z, v.w, ph.y, pl.y);
    ((uint2*)hi)[i] = ph;
    ((uint2*)lo)[i] = pl;
}

// ---------------- concat Wq|Wk|Wv (all layers) + split ----------------
__global__ void concat_split_qkv(const float* __restrict__ Wq, const float* __restrict__ Wk,
                                 const float* __restrict__ Wv,
                                 bf16* __restrict__ hi, bf16* __restrict__ lo) {
    int idx4 = blockIdx.x * 256 + threadIdx.x;
    if (idx4 >= NLAYER * DIM * (QKVD / 4)) return;
    int l   = idx4 / (DIM * (QKVD / 4));
    int r   = idx4 % (DIM * (QKVD / 4));
    int row = r / (QKVD / 4);
    int col = (r % (QKVD / 4)) * 4;
    float4 v;
    if (col < DIM)            v = *(const float4*)(Wq + ((size_t)l * DIM + row) * DIM + col);
    else if (col < DIM + KVD) v = *(const float4*)(Wk + ((size_t)l * DIM + row) * KVD + (col - DIM));
    else                      v = *(const float4*)(Wv + ((size_t)l * DIM + row) * KVD + (col - DIM - KVD));
    uint2 ph, pl;
    split2(v.x, v.y, ph.x, pl.x);
    split2(v.z, v.w, ph.y, pl.y);
    size_t o = ((size_t)l * DIM + row) * QKVD + col;
    *(uint2*)(hi + o) = ph;
    *(uint2*)(lo + o) = pl;
}

// ---------------- layernorm -> split bf16 hi/lo ----------------
__global__ __launch_bounds__(256) void ln_kernel(const float* __restrict__ x,
                                                 const float* __restrict__ g,
                                                 const float* __restrict__ b,
                                                 bf16* __restrict__ yhi,
                                                 bf16* __restrict__ ylo) {
    int row = blockIdx.x;
    int tid = threadIdx.x;
    const float* xr = x + (size_t)row * DIM;
    float4 v = *(const float4*)(xr + tid * 4);
    float sum = v.x + v.y + v.z + v.w;
    float sq  = v.x*v.x + v.y*v.y + v.z*v.z + v.w*v.w;
    #pragma unroll
    for (int o = 16; o > 0; o >>= 1) {
        sum += __shfl_xor_sync(0xffffffffu, sum, o);
        sq  += __shfl_xor_sync(0xffffffffu, sq,  o);
    }
    __shared__ float sh[18];
    int wid = tid >> 5, lane = tid & 31;
    if (lane == 0) { sh[wid] = sum; sh[8 + wid] = sq; }
    __syncthreads();
    if (tid == 0) {
        float a = 0.f, c = 0.f;
        #pragma unroll
        for (int w = 0; w < 8; w++) { a += sh[w]; c += sh[8 + w]; }
        float mu  = a * (1.0f / DIM);
        float var = c * (1.0f / DIM) - mu * mu;
        sh[16] = mu;
        sh[17] = rsqrtf(var + 1e-5f);
    }
    __syncthreads();
    float mu = sh[16], rstd = sh[17];
    float4 gg = *(const float4*)(g + tid * 4);
    float4 bb = *(const float4*)(b + tid * 4);
    float o0 = (v.x - mu) * rstd * gg.x + bb.x;
    float o1 = (v.y - mu) * rstd * gg.y + bb.y;
    float o2 = (v.z - mu) * rstd * gg.z + bb.z;
    float o3 = (v.w - mu) * rstd * gg.w + bb.w;
    uint2 ph, pl;
    split2(o0, o1, ph.x, pl.x);
    split2(o2, o3, ph.y, pl.y);
    *(uint2*)(yhi + (size_t)row * DIM + tid * 4) = ph;
    *(uint2*)(ylo + (size_t)row * DIM + tid * 4) = pl;
}

// =====================================================================
// bf16 split-GEMM — R12 config (best): 256 threads / 8 warps
// (2M x 4N, 64x32 warp tiles), BK=64, 3-stage cp.async, M-fastest grid.
// =====================================================================
#define BK     64
#define SPADA  72
#define SPADB  136
#define NSTAGE 3

__device__ __forceinline__ void mma16816(float* c, const unsigned* a, const unsigned* b) {
    asm volatile(
        "mma.sync.aligned.m16n8k16.row.col.f32.bf16.bf16.f32 "
        "{%0,%1,%2,%3}, {%4,%5,%6,%7}, {%8,%9}, {%0,%1,%2,%3};\n"
        : "+f"(c[0]), "+f"(c[1]), "+f"(c[2]), "+f"(c[3])
        : "r"(a[0]), "r"(a[1]), "r"(a[2]), "r"(a[3]), "r"(b[0]), "r"(b[1]));
}
__device__ __forceinline__ void ldsm4(unsigned* r, unsigned addr) {
    asm volatile("ldmatrix.sync.aligned.m8n8.x4.shared.b16 {%0,%1,%2,%3}, [%4];\n"
                 : "=r"(r[0]), "=r"(r[1]), "=r"(r[2]), "=r"(r[3]) : "r"(addr));
}
__device__ __forceinline__ void ldsm4t(unsigned* r, unsigned addr) {
    asm volatile("ldmatrix.sync.aligned.m8n8.x4.trans.shared.b16 {%0,%1,%2,%3}, [%4];\n"
                 : "=r"(r[0]), "=r"(r[1]), "=r"(r[2]), "=r"(r[3]) : "r"(addr));
}
__device__ __forceinline__ void cpa16(unsigned dst, const void* src) {
    asm volatile("cp.async.cg.shared.global [%0], [%1], 16;\n" :: "r"(dst), "l"(src) : "memory");
}
__device__ __forceinline__ void cpa_commit() {
    asm volatile("cp.async.commit_group;\n" ::: "memory");
}
template <int Npend>
__device__ __forceinline__ void cpa_wait() {
    asm volatile("cp.async.wait_group %0;\n" :: "n"(Npend) : "memory");
}

template <int EPI>
__global__ __launch_bounds__(256, 1) void gemm_bf(const bf16* __restrict__ Ah_g,
                                                  const bf16* __restrict__ Al_g,
                                                  const bf16* __restrict__ Bh_g,
                                                  const bf16* __restrict__ Bl_g,
                                                  const float* __restrict__ bias,
                                                  const float* __restrict__ res,
                                                  float* __restrict__ C,
                                                  bf16* __restrict__ Chi,
                                                  bf16* __restrict__ Clo,
                                                  int M, int N, int K) {
    __shared__ __align__(16) bf16 Ah[NSTAGE][128][SPADA], Al[NSTAGE][128][SPADA];
    __shared__ __align__(16) bf16 Bh[NSTAGE][BK][SPADB],  Bl[NSTAGE][BK][SPADB];

    int tid = threadIdx.x;
    int bm = blockIdx.x * 128, bn = blockIdx.y * 128;   // M-fastest
    int wid = tid >> 5, lane = tid & 31;
    int wm = (wid & 1) * 64;
    int wn = (wid >> 1) * 32;
    int g  = lane >> 2, tg = lane & 3;

    int a_row[4], a_col[4], b_row[4], b_col[4];
    #pragma unroll
    for (int i = 0; i < 4; i++) {
        int idx = tid + i * 256;
        a_row[i] = idx >> 3;  a_col[i] = (idx & 7) * 8;
        b_row[i] = idx >> 4;  b_col[i] = (idx & 15) * 8;
    }

    unsigned baseAh[NSTAGE], baseAl[NSTAGE], baseBh[NSTAGE], baseBl[NSTAGE];
    #pragma unroll
    for (int s = 0; s < NSTAGE; s++) {
        baseAh[s] = (unsigned)__cvta_generic_to_shared(&Ah[s][0][0]);
        baseAl[s] = (unsigned)__cvta_generic_to_shared(&Al[s][0][0]);
        baseBh[s] = (unsigned)__cvta_generic_to_shared(&Bh[s][0][0]);
        baseBl[s] = (unsigned)__cvta_generic_to_shared(&Bl[s][0][0]);
    }
    unsigned dA[4], dB[4];
    #pragma unroll
    for (int i = 0; i < 4; i++) {
        dA[i] = (a_row[i] * SPADA + a_col[i]) * 2;
        dB[i] = (b_row[i] * SPADB + b_col[i]) * 2;
    }

    auto issue = [&](int s, int k0) {
        #pragma unroll
        for (int i = 0; i < 4; i++) {
            size_t ao = (size_t)(bm + a_row[i]) * K + k0 + a_col[i];
            size_t bo = (size_t)(k0 + b_row[i]) * N + bn + b_col[i];
            cpa16(baseAh[s] + dA[i], Ah_g + ao);
            cpa16(baseAl[s] + dA[i], Al_g + ao);
            cpa16(baseBh[s] + dB[i], Bh_g + bo);
            cpa16(baseBl[s] + dB[i], Bl_g + bo);
        }
    };

    int a_row_l  = wm + (lane & 15);
    int a_col_l  = (lane >> 4) * 8;
    int b_krow_l = lane & 15;
    int b_ncol_l = wn + (lane >> 4) * 8;

    float acc[4][4][4];
    #pragma unroll
    for (int a = 0; a < 4; a++)
        #pragma unroll
        for (int b = 0; b < 4; b++)
            #pragma unroll
            for (int c = 0; c < 4; c++) acc[a][b][c] = 0.f;

    auto compute = [&](int s) {
        #pragma unroll
        for (int kk = 0; kk < BK; kk += 16) {
            unsigned afh[4][4], afl[4][4];
            #pragma unroll
            for (int mt = 0; mt < 4; mt++) {
                unsigned off = ((a_row_l + mt * 16) * SPADA + a_col_l + kk) * 2;
                ldsm4(afh[mt], baseAh[s] + off);
                ldsm4(afl[mt], baseAl[s] + off);
            }
            unsigned bfh[2][4], bfl[2][4];
            #pragma unroll
            for (int p = 0; p < 2; p++) {
                unsigned off = ((kk + b_krow_l) * SPADB + b_ncol_l + p * 16) * 2;
                ldsm4t(bfh[p], baseBh[s] + off);
                ldsm4t(bfl[p], baseBl[s] + off);
            }
            #pragma unroll
            for (int mt = 0; mt < 4; mt++) {
                #pragma unroll
                for (int nt = 0; nt < 4; nt++) {
                    unsigned* bh2 = &bfh[nt >> 1][(nt & 1) * 2];
                    unsigned* bl2 = &bfl[nt >> 1][(nt & 1) * 2];
                    mma16816(acc[mt][nt], afh[mt], bh2);
                    mma16816(acc[mt][nt], afh[mt], bl2);
                    mma16816(acc[mt][nt], afl[mt], bh2);
                }
            }
        }
    };

    int nchunk = K / BK;
    issue(0, 0);       cpa_commit();
    issue(1, BK);      cpa_commit();
    for (int ch = 0; ch < nchunk; ch++) {
        cpa_wait<1>();
        __syncthreads();
        int nx = ch + 2;
        if (nx < nchunk) issue(nx % NSTAGE, nx * BK);
        cpa_commit();
        compute(ch % NSTAGE);
    }

    #pragma unroll
    for (int mt = 0; mt < 4; mt++) {
        #pragma unroll
        for (int nt = 0; nt < 4; nt++) {
            int row = bm + wm + mt * 16 + g;
            int col = bn + wn + nt * 8 + tg * 2;
            float2 o0 = make_float2(acc[mt][nt][0], acc[mt][nt][1]);
            float2 o1 = make_float2(acc[mt][nt][2], acc[mt][nt][3]);
            if (EPI >= 1) {
                float2 bb = *(const float2*)(bias + col);
                o0.x += bb.x; o0.y += bb.y; o1.x += bb.x; o1.y += bb.y;
            }
            if (EPI == 3) {
                float2 r0 = *(const float2*)(res + (size_t)row * N + col);
                float2 r1 = *(const float2*)(res + (size_t)(row + 8) * N + col);
                o0.x += r0.x; o0.y += r0.y; o1.x += r1.x; o1.y += r1.y;
            }
            if (EPI == 4) {
                o0.x = fmaxf(o0.x, 0.f); o0.y = fmaxf(o0.y, 0.f);
                o1.x = fmaxf(o1.x, 0.f); o1.y = fmaxf(o1.y, 0.f);
                unsigned h0, l0, h1, l1;
                split2(o0.x, o0.y, h0, l0);
                split2(o1.x, o1.y, h1, l1);
                *(unsigned*)(Chi + (size_t)row * N + col)       = h0;
                *(unsigned*)(Clo + (size_t)row * N + col)       = l0;
                *(unsigned*)(Chi + (size_t)(row + 8) * N + col) = h1;
                *(unsigned*)(Clo + (size_t)(row + 8) * N + col) = l1;
            } else {
                *(float2*)(C + (size_t)row * N + col) = o0;
                *(float2*)(C + (size_t)(row + 8) * N + col) = o1;
            }
        }
    }
}

// ---------------- fused causal GQA attention, lane-pair split over HS ----------------
// 128 threads / 64 queries: lanes (l, l+16) of a warp handle one query,
// each owning 32 of the 64 head dims. QK partial dots combined via shfl.
__global__ __launch_bounds__(128) void attn_kernel(const float* __restrict__ QKV,
                                                   bf16* __restrict__ Yhi,
                                                   bf16* __restrict__ Ylo) {
    __shared__ __align__(16) float ks[64][64];
    __shared__ __align__(16) float vs[64][64];
    __shared__ float ss[64][65];

    int itile = blockIdx.x;
    int h     = blockIdx.y;
    int b     = blockIdx.z;
    int kvh   = h >> 2;
    int tid   = threadIdx.x;
    int w     = tid >> 5, lane = tid & 31;
    int qi    = w * 16 + (lane & 15);        // query within tile (0..63)
    int half  = lane >> 4;                   // 0 or 1
    int d0    = half * 32;
    int i     = itile * 64 + qi;

    const float scale = 0.125f;
    float q[32], o[32];
    const float* qrow = QKV + ((size_t)(b * SEQ + i)) * QKVD + h * HSZ + d0;
    #pragma unroll
    for (int d = 0; d < 32; d += 4) {
        float4 t = *(const float4*)(qrow + d);
        q[d] = t.x * scale; q[d+1] = t.y * scale; q[d+2] = t.z * scale; q[d+3] = t.w * scale;
    }
    #pragma unroll
    for (int d = 0; d < 32; d++) o[d] = 0.f;
    float m = -1e30f, l = 0.f;

    for (int j0 = 0; j0 <= itile * 64; j0 += 64) {
        // cooperative tile load: 128 threads x 8 float4 per array
        #pragma unroll
        for (int e = 0; e < 8; e++) {
            int idx = tid + e * 128;         // 0..1023 float4 slots
            int row = idx >> 4, col = (idx & 15) * 4;
            const float* krow = QKV + ((size_t)(b * SEQ + j0 + row)) * QKVD + DIM + kvh * HSZ;
            *(float4*)&ks[row][col] = *(const float4*)(krow + col);
            *(float4*)&vs[row][col] = *(const float4*)(krow + KVD + col);
        }
        __syncthreads();

        float mt = m;
        #pragma unroll 4
        for (int j = 0; j < 64; j++) {
            float part = 0.f;
            #pragma unroll
            for (int d = 0; d < 32; d += 4) {
                float4 kk = *(const float4*)&ks[j][d0 + d];
                part = fmaf(q[d],   kk.x, part);
                part = fmaf(q[d+1], kk.y, part);
                part = fmaf(q[d+2], kk.z, part);
                part = fmaf(q[d+3], kk.w, part);
            }
            float full = part + __shfl_xor_sync(0xffffffffu, part, 16);
            if (j0 + j > i) full = -1e30f;
            if (half == 0) ss[qi][j] = full;
            mt = fmaxf(mt, full);
        }
        __syncwarp();

        float corr = __expf(m - mt);
        l *= corr;
        #pragma unroll
        for (int d = 0; d < 32; d++) o[d] *= corr;

        #pragma unroll 2
        for (int j = 0; j < 64; j++) {
            float p = __expf(ss[qi][j] - mt);
            l += p;
            #pragma unroll
            for (int d = 0; d < 32; d += 4) {
                float4 vv = *(const float4*)&vs[j][d0 + d];
                o[d]   = fmaf(p, vv.x, o[d]);
                o[d+1] = fmaf(p, vv.y, o[d+1]);
                o[d+2] = fmaf(p, vv.z, o[d+2]);
                o[d+3] = fmaf(p, vv.w, o[d+3]);
            }
        }
        m = mt;
        __syncthreads();
    }

    float inv = 1.0f / l;
    size_t yo = ((size_t)(b * SEQ + i)) * DIM + h * HSZ + d0;
    #pragma unroll
    for (int d = 0; d < 32; d += 4) {
        uint2 ph, pl;
        split2(o[d] * inv,   o[d+1] * inv, ph.x, pl.x);
        split2(o[d+2] * inv, o[d+3] * inv, ph.y, pl.y);
        *(uint2*)(Yhi + yo + d) = ph;
        *(uint2*)(Ylo + yo + d) = pl;
    }
}

// ---------------- host ----------------
template <typename Tp>
static void* sym_addr(Tp& s) {
    void* p = nullptr;
    cudaGetSymbolAddress(&p, s);
    return p;
}

static void launch_gemm(int epi, const bf16* Ah, const bf16* Al,
                        const bf16* Bh, const bf16* Bl,
                        const float* bias, const float* res,
                        float* C, bf16* Chi, bf16* Clo, int M, int N, int K) {
    dim3 grid(M / 128, N / 128);   // M-fastest
    switch (epi) {
        case 0: gemm_bf<0><<<grid, 256>>>(Ah, Al, Bh, Bl, bias, res, C, Chi, Clo, M, N, K); break;
        case 1: gemm_bf<1><<<grid, 256>>>(Ah, Al, Bh, Bl, bias, res, C, Chi, Clo, M, N, K); break;
        case 3: gemm_bf<3><<<grid, 256>>>(Ah, Al, Bh, Bl, bias, res, C, Chi, Clo, M, N, K); break;
        case 4: gemm_bf<4><<<grid, 256>>>(Ah, Al, Bh, Bl, bias, res, C, Chi, Clo, M, N, K); break;
    }
}

extern "C" void kernel_launch(void* const* d_in, const int* in_sizes, int n_in,
                              void* d_out, int out_size) {
    const int*   tok   = (const int*)  d_in[0];
    const float* te    = (const float*)d_in[1];
    const float* pe    = (const float*)d_in[2];
    const float* ln1g  = (const float*)d_in[3];
    const float* ln1b  = (const float*)d_in[4];
    const float* Wq    = (const float*)d_in[5];
    const float* Wk    = (const float*)d_in[6];
    const float* Wv    = (const float*)d_in[7];
    const float* Wo    = (const float*)d_in[8];
    const float* bo    = (const float*)d_in[9];
    const float* ln2g  = (const float*)d_in[10];
    const float* ln2b  = (const float*)d_in[11];
    const float* W1    = (const float*)d_in[12];
    const float* b1    = (const float*)d_in[13];
    const float* W2    = (const float*)d_in[14];
    const float* b2    = (const float*)d_in[15];
    const float* lnfg  = (const float*)d_in[16];
    const float* lnfb  = (const float*)d_in[17];
    const float* Wlm   = (const float*)d_in[18];
    const float* blm   = (const float*)d_in[19];
    float* out = (float*)d_out;

    float* x    = (float*)sym_addr(g_x);
    float* qkv  = (float*)sym_addr(g_qkv);
    bf16* h_hi  = (bf16*)sym_addr(g_h_hi),  * h_lo  = (bf16*)sym_addr(g_h_lo);
    bf16* y_hi  = (bf16*)sym_addr(g_y_hi),  * y_lo  = (bf16*)sym_addr(g_y_lo);
    bf16* ff_hi = (bf16*)sym_addr(g_ff_hi), * ff_lo = (bf16*)sym_addr(g_ff_lo);
    bf16* wqkv_hi = (bf16*)sym_addr(g_wqkv_hi), * wqkv_lo = (bf16*)sym_addr(g_wqkv_lo);
    bf16* wo_hi   = (bf16*)sym_addr(g_wo_hi),   * wo_lo   = (bf16*)sym_addr(g_wo_lo);
    bf16* w1_hi   = (bf16*)sym_addr(g_w1_hi),   * w1_lo   = (bf16*)sym_addr(g_w1_lo);
    bf16* w2_hi   = (bf16*)sym_addr(g_w2_hi),   * w2_lo   = (bf16*)sym_addr(g_w2_lo);
    bf16* wlm_hi  = (bf16*)sym_addr(g_wlm_hi),  * wlm_lo  = (bf16*)sym_addr(g_wlm_lo);

    cudaStream_t s2;
    cudaEvent_t evFork, evJoin;
    cudaStreamCreateWithFlags(&s2, cudaStreamNonBlocking);
    cudaEventCreateWithFlags(&evFork, cudaEventDisableTiming);
    cudaEventCreateWithFlags(&evJoin, cudaEventDisableTiming);

    {
        int n4 = NLAYER * DIM * (QKVD / 4);
        concat_split_qkv<<<(n4 + 255) / 256, 256>>>(Wq, Wk, Wv, wqkv_hi, wqkv_lo);
    }
    embed_kernel<<<NTOK * DIM / 256, 256>>>(tok, te, pe, x);

    cudaEventRecord(evFork, 0);
    cudaStreamWaitEvent(s2, evFork, 0);
    {
        int n4;
        n4 = NLAYER * DIM * DIM / 4;
        split_kernel<<<(n4 + 255) / 256, 256, 0, s2>>>(Wo, wo_hi, wo_lo, n4);
        n4 = NLAYER * DIM * FFD / 4;
        split_kernel<<<(n4 + 255) / 256, 256, 0, s2>>>(W1, w1_hi, w1_lo, n4);
        n4 = NLAYER * FFD * DIM / 4;
        split_kernel<<<(n4 + 255) / 256, 256, 0, s2>>>(W2, w2_hi, w2_lo, n4);
        n4 = DIM * VOCAB / 4;
        split_kernel<<<(n4 + 255) / 256, 256, 0, s2>>>(Wlm, wlm_hi, wlm_lo, n4);
    }
    cudaEventRecord(evJoin, s2);

    bool joined = false;
    for (int l = 0; l < NLAYER; l++) {
        const bf16* wqh = wqkv_hi + (size_t)l * DIM * QKVD;
        const bf16* wql = wqkv_lo + (size_t)l * DIM * QKVD;
        const bf16* woh = wo_hi   + (size_t)l * DIM * DIM;
        const bf16* wol = wo_lo   + (size_t)l * DIM * DIM;
        const bf16* w1h = w1_hi   + (size_t)l * DIM * FFD;
        const bf16* w1l = w1_lo   + (size_t)l * DIM * FFD;
        const bf16* w2h = w2_hi   + (size_t)l * FFD * DIM;
        const bf16* w2l = w2_lo   + (size_t)l * FFD * DIM;

        ln_kernel<<<NTOK, 256>>>(x, ln1g + l * DIM, ln1b + l * DIM, h_hi, h_lo);

        launch_gemm(0, h_hi, h_lo, wqh, wql, nullptr, nullptr, qkv, nullptr, nullptr,
                    NTOK, QKVD, DIM);

        attn_kernel<<<dim3(SEQ / 64, NH, NB), 128>>>(qkv, y_hi, y_lo);

        if (!joined) { cudaStreamWaitEvent(0, evJoin, 0); joined = true; }

        launch_gemm(3, y_hi, y_lo, woh, wol, bo + l * DIM, x, x, nullptr, nullptr,
                    NTOK, DIM, DIM);

        ln_kernel<<<NTOK, 256>>>(x, ln2g + l * DIM, ln2b + l * DIM, h_hi, h_lo);

        launch_gemm(4, h_hi, h_lo, w1h, w1l, b1 + (size_t)l * FFD, nullptr,
                    nullptr, ff_hi, ff_lo, NTOK, FFD, DIM);
        launch_gemm(3, ff_hi, ff_lo, w2h, w2l, b2 + l * DIM, x, x, nullptr, nullptr,
                    NTOK, DIM, FFD);
    }

    ln_kernel<<<NTOK, 256>>>(x, lnfg, lnfb, h_hi, h_lo);
    launch_gemm(1, h_hi, h_lo, wlm_hi, wlm_lo, blm, nullptr, out, nullptr, nullptr,
                NTOK, VOCAB, DIM);

    cudaEventDestroy(evFork);
    cudaEventDestroy(evJoin);
    cudaStreamDestroy(s2);
}